// round 13
// baseline (speedup 1.0000x reference)
#include <cuda_runtime.h>
#include <cuda_fp16.h>
#include <math.h>
#include <float.h>
#include <stdint.h>

#define NB    8
#define LSEQ  4096
#define HIN   1024
#define HD    1024
#define MTOT  (NB * LSEQ)        // 32768

#define BM    128
#define BNC   128                // combined N per CTA (64 z + 64 h_inter)
#define BNR   64                 // real channels per CTA
#define BK    64
#define STAGES 2
#define KIT   (HIN / BK)         // 16
#define NTHR  256

#define PITCHH 72                // halves per row (144 B)
#define AHALF  (BM * PITCHH)     // 9216
#define BHALF  (BNC * PITCHH)    // 9216
#define STAGEH (AHALF + BHALF)   // 18432 halves = 36864 B
#define SMEM_BYTES (STAGES * STAGEH * 2)   // 73728
#define EPIPITCH 132
#define SEGSM_OFF (BM * EPIPITCH)

#define NCH   32                 // scan chunks (CHK == BM)
#define CHK   (LSEQ / NCH)       // 128
#define TCH   (NB * HD)          // 8192 channels

// Static scratch (no runtime allocation allowed)
__device__ __half g_wh[(size_t)2 * HD * HIN];     // fp16 W only
__device__ float  g_a [(size_t)MTOT * HD];        // segment-local prefix Pl
__device__ float  g_b [(size_t)MTOT * HD];        // segment-local value  vl
__device__ float  g_init[NCH * TCH];              // incoming log_h per chunk [c][t]
__device__ float  g_Pend[(size_t)TCH * NCH];      // chunk endpoint P, [t][c]
__device__ float  g_Vend[(size_t)TCH * NCH];      // chunk endpoint V, [t][c]
__device__ float  g_segP[(size_t)NCH * 4 * TCH];  // per-seg incoming P
__device__ float  g_segV[(size_t)NCH * 4 * TCH];  // per-seg incoming V

__device__ __forceinline__ uint32_t smem_u32(const void* p) {
    uint32_t a;
    asm("{ .reg .u64 t; cvta.to.shared.u64 t, %1; cvt.u32.u64 %0, t; }" : "=r"(a) : "l"(p));
    return a;
}
__device__ __forceinline__ void cp16(uint32_t dst, const void* src) {
    asm volatile("cp.async.cg.shared.global [%0], [%1], 16;" :: "r"(dst), "l"(src) : "memory");
}
__device__ __forceinline__ void ldsm4(uint32_t& r0, uint32_t& r1, uint32_t& r2, uint32_t& r3,
                                      uint32_t addr) {
    asm volatile("ldmatrix.sync.aligned.m8n8.x4.shared.b16 {%0,%1,%2,%3}, [%4];"
                 : "=r"(r0), "=r"(r1), "=r"(r2), "=r"(r3) : "r"(addr));
}
// pack two fp32 -> fp16x2 (lo, hi) with RN
__device__ __forceinline__ uint32_t f2h2(float lo, float hi) {
    uint32_t r;
    asm("cvt.rn.f16x2.f32 %0, %1, %2;" : "=r"(r) : "f"(hi), "f"(lo));
    return r;
}
__device__ __forceinline__ float logaddexpf(float u, float v) {
    float mx = fmaxf(u, v), mn = fminf(u, v);
    return mx + __logf(1.f + __expf(mn - mx));
}

// ---------------------------------------------------------------------------
// Pre-convert W only (x converted inline in the GEMM)
// ---------------------------------------------------------------------------
__global__ void __launch_bounds__(256) cvt_kernel(const float* __restrict__ W)
{
    size_t i = (size_t)blockIdx.x * blockDim.x + threadIdx.x;
    size_t stride = (size_t)gridDim.x * blockDim.x;
    const float4* w4 = (const float4*)W;
    __half2* wo = (__half2*)g_wh;
    size_t nw = (size_t)2 * HD * HIN / 4;
    for (size_t j = i; j < nw; j += stride) {
        float4 v = w4[j];
        wo[j * 2 + 0] = __floats2half2_rn(v.x, v.y);
        wo[j * 2 + 1] = __floats2half2_rn(v.z, v.w);
    }
}

// ---------------------------------------------------------------------------
// fp16 mma.sync GEMM (2 CTAs/SM) + inline x cvt + activation + segment scan
// ---------------------------------------------------------------------------
__global__ void __launch_bounds__(NTHR, 2) gemm_kernel(
    const float* __restrict__ x, const float* __restrict__ bias)
{
    extern __shared__ __half smh[];
    float* smf = (float*)smh;
    const int tid  = threadIdx.x;
    const int wid  = tid >> 5;
    const int lane = tid & 31;
    const int g    = lane >> 2;
    const int c    = lane & 3;
    const int m0   = blockIdx.y * BM;
    const int h0   = blockIdx.x * BNR;
    const uint32_t sbase = smem_u32(smh);

    // A: direct fp32 LDG + cvt + STS. 4 chunks (16B fp16 each) per thread.
    const float* gA[4]; uint32_t dA[4];
#pragma unroll
    for (int i = 0; i < 4; i++) {
        int ci = tid + i * NTHR;          // 0..1023
        int row = ci >> 3, ch = ci & 7;
        gA[i] = x + (size_t)(m0 + row) * HIN + ch * 8;
        dA[i] = (uint32_t)(row * 144 + ch * 16);
    }
    // B: cp.async fp16, 4 chunks per thread
    const __half* gB[4]; uint32_t dB[4];
#pragma unroll
    for (int i = 0; i < 4; i++) {
        int ci = tid + i * NTHR;
        int row = ci >> 3, ch = ci & 7;
        int wrow = (row < 64) ? (h0 + row) : (HD + h0 + row - 64);
        gB[i] = g_wh + (size_t)wrow * HIN + ch * 8;
        dB[i] = (uint32_t)(AHALF * 2 + row * 144 + ch * 16);
    }

#define ISSUE_B(KT) do {                                                      \
    int _kt = (KT);                                                           \
    if (_kt < KIT) {                                                          \
        uint32_t _s = sbase + (uint32_t)(_kt % STAGES) * (STAGEH * 2);        \
        _Pragma("unroll")                                                     \
        for (int _i = 0; _i < 4; _i++) cp16(_s + dB[_i], gB[_i] + _kt * BK);  \
    }                                                                         \
    asm volatile("cp.async.commit_group;" ::: "memory");                      \
} while (0)

#define FILL_A(KT) do {                                                       \
    int _kt = (KT);                                                           \
    if (_kt < KIT) {                                                          \
        uint32_t _s = sbase + (uint32_t)(_kt % STAGES) * (STAGEH * 2);        \
        _Pragma("unroll")                                                     \
        for (int _i = 0; _i < 4; _i++) {                                      \
            const float4* _p = (const float4*)(gA[_i] + _kt * BK);            \
            float4 _v0 = __ldg(_p);                                           \
            float4 _v1 = __ldg(_p + 1);                                       \
            uint32_t _h0 = f2h2(_v0.x, _v0.y);                                \
            uint32_t _h1 = f2h2(_v0.z, _v0.w);                                \
            uint32_t _h2 = f2h2(_v1.x, _v1.y);                                \
            uint32_t _h3 = f2h2(_v1.z, _v1.w);                                \
            asm volatile("st.shared.v4.b32 [%0], {%1,%2,%3,%4};"              \
                :: "r"(_s + dA[_i]), "r"(_h0), "r"(_h1), "r"(_h2), "r"(_h3)   \
                : "memory");                                                  \
        }                                                                     \
    }                                                                         \
} while (0)

    FILL_A(0);
    ISSUE_B(0);

    // 8 warps: 4(M) x 2(Ncomb); warp tile 32 x 64 -> 2 Mtiles x 8 Ntiles
    const int mw = (wid >> 1) * 32;
    const int nw = (wid & 1) * 64;

    const int aj = lane >> 3;
    const int arow = mw + (aj & 1) * 8 + (lane & 7);
    const uint32_t aoff = (uint32_t)(arow * 144 + (aj >> 1) * 16);
    const int bj = lane >> 3;
    const int brow_base = nw + (bj >> 1) * 8 + (lane & 7);
    const uint32_t bkoff = (uint32_t)((bj & 1) * 16);

    float d[2][8][4];
#pragma unroll
    for (int mt = 0; mt < 2; mt++)
#pragma unroll
        for (int nt = 0; nt < 8; nt++)
#pragma unroll
            for (int q = 0; q < 4; q++) d[mt][nt][q] = 0.f;

    for (int kt = 0; kt < KIT; kt++) {
        ISSUE_B(kt + 1);
        asm volatile("cp.async.wait_group 1;" ::: "memory");
        __syncthreads();   // B(kt) + A(kt) STS visible to all

        FILL_A(kt + 1);    // writes stage (kt+1)%2 while MMAs read kt%2

        const uint32_t sa = sbase + (uint32_t)(kt % STAGES) * (STAGEH * 2);
        const uint32_t sb = sa + AHALF * 2;

        uint32_t afc[2][4], afn[2][4];
#pragma unroll
        for (int mt = 0; mt < 2; mt++)
            ldsm4(afc[mt][0], afc[mt][1], afc[mt][2], afc[mt][3],
                  sa + aoff + (uint32_t)(mt * 16 * 144));

#pragma unroll
        for (int s16 = 0; s16 < 4; s16++) {
            const uint32_t kbyte = (uint32_t)(s16 * 32);
            if (s16 < 3) {
#pragma unroll
                for (int mt = 0; mt < 2; mt++)
                    ldsm4(afn[mt][0], afn[mt][1], afn[mt][2], afn[mt][3],
                          sa + aoff + (uint32_t)(mt * 16 * 144) + kbyte + 32);
            }
            uint32_t bf[8][2];
#pragma unroll
            for (int p = 0; p < 4; p++) {
                int ntp = p * 2;
                ldsm4(bf[ntp][0], bf[ntp][1], bf[ntp+1][0], bf[ntp+1][1],
                      sb + (uint32_t)((brow_base + ntp * 8) * 144) + bkoff + kbyte);
            }
#pragma unroll
            for (int mt = 0; mt < 2; mt++)
#pragma unroll
                for (int nt = 0; nt < 8; nt++) {
                    asm volatile(
                        "mma.sync.aligned.m16n8k16.row.col.f32.f16.f16.f32 "
                        "{%0,%1,%2,%3}, {%4,%5,%6,%7}, {%8,%9}, {%0,%1,%2,%3};"
                        : "+f"(d[mt][nt][0]), "+f"(d[mt][nt][1]),
                          "+f"(d[mt][nt][2]), "+f"(d[mt][nt][3])
                        : "r"(afc[mt][0]), "r"(afc[mt][1]), "r"(afc[mt][2]), "r"(afc[mt][3]),
                          "r"(bf[nt][0]), "r"(bf[nt][1]));
                }
#pragma unroll
            for (int mt = 0; mt < 2; mt++)
#pragma unroll
                for (int q = 0; q < 4; q++) afc[mt][q] = afn[mt][q];
        }
        __syncthreads();   // readers of stage kt%2 done before it's refilled
    }

    // ---- step 1: acc -> smem tile (z | h_inter), pitch 132
#pragma unroll
    for (int mt = 0; mt < 2; mt++)
#pragma unroll
        for (int nt = 0; nt < 8; nt++) {
            int r   = mw + mt * 16 + g;
            int col = nw + nt * 8 + 2 * c;
            *(float2*)&smf[r * EPIPITCH + col]       = make_float2(d[mt][nt][0], d[mt][nt][1]);
            *(float2*)&smf[(r + 8) * EPIPITCH + col] = make_float2(d[mt][nt][2], d[mt][nt][3]);
        }
    __syncthreads();

    // ---- step 2: fused activation + segment-local scan; streaming stores
    const int sch = tid & 63;
    const int seg = tid >> 6;
    float* sPend = smf + SEGSM_OFF;             // [4][64]
    float* sVend = smf + SEGSM_OFF + 4 * 64;
    const float bz = __ldg(bias + h0 + sch);
    const float bh = __ldg(bias + HD + h0 + sch);
    {
        float P = 0.f, v = -FLT_MAX;
#pragma unroll 4
        for (int l = seg * 32; l < seg * 32 + 32; l++) {
            float z  = smf[l * EPIPITCH + sch]      + bz;
            float hi = smf[l * EPIPITCH + 64 + sch] + bh;
            float s  = fmaxf(-z, 0.f) + __logf(1.f + __expf(-fabsf(z)));
            float A  = -(z + s);
            float ltH = (hi >= 0.f) ? __logf(hi + 0.5f)
                                    : hi - __logf(1.f + __expf(hi));
            float B  = ltH - s;
            P += A;
            v = logaddexpf(A + v, B);
            size_t idx = (size_t)(m0 + l) * HD + h0 + sch;
            __stcs(&g_a[idx], P);
            __stcs(&g_b[idx], v);
        }
        sPend[seg * 64 + sch] = P;
        sVend[seg * 64 + sch] = v;
    }
    __syncthreads();

    // ---- step 3: combine seg summaries -> per-seg incoming + chunk endpoint
    if (tid < 64) {
        int n   = m0 >> 12;
        int cch = (m0 & (LSEQ - 1)) >> 7;
        float Pb = 0.f, V = -FLT_MAX;
#pragma unroll
        for (int s = 0; s < 4; s++) {
            float Pe = sPend[s * 64 + tid];
            float Ve = sVend[s * 64 + tid];
            size_t sidx = ((size_t)(cch * 4 + s) * NB + n) * HD + h0 + tid;
            g_segP[sidx] = Pb;
            g_segV[sidx] = V;
            V  = logaddexpf(Pe + V, Ve);
            Pb += Pe;
        }
        size_t eidx = ((size_t)n * HD + h0 + tid) * NCH + cch;
        g_Pend[eidx] = Pb;
        g_Vend[eidx] = V;
    }
}

// ---------------------------------------------------------------------------
// Scan phase 2: one warp per (n,h); Kogge-Stone scan over 32 chunk states
// ---------------------------------------------------------------------------
__global__ void __launch_bounds__(256) scan_p2_kernel(const float* __restrict__ hx)
{
    int w = (blockIdx.x * blockDim.x + threadIdx.x) >> 5;
    int lane = threadIdx.x & 31;
    if (w >= TCH) return;

    float P = g_Pend[(size_t)w * NCH + lane];
    float V = g_Vend[(size_t)w * NCH + lane];

#pragma unroll
    for (int dlt = 1; dlt < 32; dlt <<= 1) {
        float Pp = __shfl_up_sync(0xFFFFFFFF, P, dlt);
        float Vp = __shfl_up_sync(0xFFFFFFFF, V, dlt);
        if (lane >= dlt) {
            V = logaddexpf(P + Vp, V);
            P = P + Pp;
        }
    }
    float Pe = __shfl_up_sync(0xFFFFFFFF, P, 1);
    float Ve = __shfl_up_sync(0xFFFFFFFF, V, 1);
    if (lane == 0) { Pe = 0.f; Ve = -FLT_MAX; }

    float logh0 = __logf(hx[w]);
    g_init[lane * TCH + w] = logaddexpf(Pe + logh0, Ve);
}

// ---------------------------------------------------------------------------
// Scan phase 3: J = logaddexp(Pb+I, V); out = exp(logaddexp(Pl + J, vl))
// ---------------------------------------------------------------------------
__global__ void __launch_bounds__(256) scan_p3_kernel(float* __restrict__ out)
{
    size_t i = (size_t)blockIdx.x * blockDim.x + threadIdx.x;
    size_t stride = (size_t)gridDim.x * blockDim.x;
    const float4* pa4 = (const float4*)g_a;
    const float4* pb4 = (const float4*)g_b;
    const float4* pi4 = (const float4*)g_init;
    const float4* sp4 = (const float4*)g_segP;
    const float4* sv4 = (const float4*)g_segV;
    float4* out4 = (float4*)out;
    size_t total = (size_t)MTOT * HD / 4;

    for (size_t j = i; j < total; j += stride) {
        size_t row = j >> 8;
        int q = (int)(j & 255);
        int l = (int)(row & (LSEQ - 1));
        int n = (int)(row >> 12);
        int c = l >> 7;
        int s = (l >> 5) & 3;
        size_t tq = (size_t)n * (HD / 4) + q;
        float4 Pl = __ldcs(&pa4[j]);
        float4 vl = __ldcs(&pb4[j]);
        float4 I  = pi4[(size_t)c * (TCH / 4) + tq];
        float4 Pb = sp4[(size_t)(c * 4 + s) * (TCH / 4) + tq];
        float4 V  = sv4[(size_t)(c * 4 + s) * (TCH / 4) + tq];
        float4 o;
        o.x = __expf(logaddexpf(Pl.x + logaddexpf(Pb.x + I.x, V.x), vl.x));
        o.y = __expf(logaddexpf(Pl.y + logaddexpf(Pb.y + I.y, V.y), vl.y));
        o.z = __expf(logaddexpf(Pl.z + logaddexpf(Pb.z + I.z, V.z), vl.z));
        o.w = __expf(logaddexpf(Pl.w + logaddexpf(Pb.w + I.w, V.w), vl.w));
        __stcs(&out4[j], o);
    }
}

extern "C" void kernel_launch(void* const* d_in, const int* in_sizes, int n_in,
                              void* d_out, int out_size) {
    const float* x    = (const float*)d_in[0];
    const float* W    = (const float*)d_in[1];
    const float* bias = (const float*)d_in[2];
    const float* hx   = (const float*)d_in[3];
    float* out = (float*)d_out;

    cudaFuncSetAttribute(gemm_kernel,
                         cudaFuncAttributeMaxDynamicSharedMemorySize, SMEM_BYTES);

    cvt_kernel<<<512, 256>>>(W);
    dim3 grid(HD / BNR, MTOT / BM);   // (16, 256)
    gemm_kernel<<<grid, NTHR, SMEM_BYTES>>>(x, bias);

    scan_p2_kernel<<<(TCH * 32) / 256, 256>>>(hx);
    scan_p3_kernel<<<4096, 256>>>(out);
}

// round 14
// speedup vs baseline: 1.1533x; 1.1533x over previous
#include <cuda_runtime.h>
#include <cuda_fp16.h>
#include <math.h>
#include <float.h>
#include <stdint.h>

#define NB    8
#define LSEQ  4096
#define HIN   1024
#define HD    1024
#define MTOT  (NB * LSEQ)        // 32768

#define BM    128
#define BNC   128                // combined N per CTA (64 z + 64 h_inter)
#define BNR   64                 // real channels per CTA
#define BK    64
#define STAGES 3
#define KIT   (HIN / BK)         // 16
#define NTHR  256

#define PITCHH 72                // halves per row (144 B)
#define AHALF  (BM * PITCHH)     // 9216
#define BHALF  (BNC * PITCHH)    // 9216
#define STAGEH (AHALF + BHALF)   // 18432 halves = 36864 B
#define SMEM_BYTES (STAGES * STAGEH * 2)   // 110592
#define EPIPITCH 132
#define SEGSM_OFF (BM * EPIPITCH)

#define NCH   32                 // scan chunks (CHK == BM)
#define CHK   (LSEQ / NCH)       // 128
#define TCH   (NB * HD)          // 8192 channels

// Static scratch (no runtime allocation allowed)
__device__ __half g_xh[(size_t)MTOT * HIN];       // fp16 x
__device__ __half g_wh[(size_t)2 * HD * HIN];     // fp16 W
__device__ float  g_a [(size_t)MTOT * HD];        // segment-local prefix Pl
__device__ float  g_b [(size_t)MTOT * HD];        // segment-local value  vl
__device__ float  g_init[NCH * TCH];              // incoming log_h per chunk [c][t]
__device__ float  g_Pend[(size_t)TCH * NCH];      // chunk endpoint P, [t][c]
__device__ float  g_Vend[(size_t)TCH * NCH];      // chunk endpoint V, [t][c]
__device__ float  g_segP[(size_t)NCH * 4 * TCH];  // per-seg incoming P
__device__ float  g_segV[(size_t)NCH * 4 * TCH];  // per-seg incoming V

__device__ __forceinline__ uint32_t smem_u32(const void* p) {
    uint32_t a;
    asm("{ .reg .u64 t; cvta.to.shared.u64 t, %1; cvt.u32.u64 %0, t; }" : "=r"(a) : "l"(p));
    return a;
}
__device__ __forceinline__ void cp16(uint32_t dst, const void* src) {
    asm volatile("cp.async.cg.shared.global [%0], [%1], 16;" :: "r"(dst), "l"(src) : "memory");
}
__device__ __forceinline__ void ldsm4(uint32_t& r0, uint32_t& r1, uint32_t& r2, uint32_t& r3,
                                      uint32_t addr) {
    asm volatile("ldmatrix.sync.aligned.m8n8.x4.shared.b16 {%0,%1,%2,%3}, [%4];"
                 : "=r"(r0), "=r"(r1), "=r"(r2), "=r"(r3) : "r"(addr));
}
__device__ __forceinline__ float logaddexpf(float u, float v) {
    float mx = fmaxf(u, v), mn = fminf(u, v);
    return mx + __logf(1.f + __expf(mn - mx));
}

// ---------------------------------------------------------------------------
// Pre-convert x, W to fp16 (rn)
// ---------------------------------------------------------------------------
__global__ void __launch_bounds__(256) cvt_kernel(
    const float* __restrict__ x, const float* __restrict__ W)
{
    size_t i = (size_t)blockIdx.x * blockDim.x + threadIdx.x;
    size_t stride = (size_t)gridDim.x * blockDim.x;
    const float4* x4 = (const float4*)x;
    __half2* xo = (__half2*)g_xh;
    size_t nx = (size_t)MTOT * HIN / 4;
    for (size_t j = i; j < nx; j += stride) {
        float4 v = x4[j];
        xo[j * 2 + 0] = __floats2half2_rn(v.x, v.y);
        xo[j * 2 + 1] = __floats2half2_rn(v.z, v.w);
    }
    const float4* w4 = (const float4*)W;
    __half2* wo = (__half2*)g_wh;
    size_t nw = (size_t)2 * HD * HIN / 4;
    for (size_t j = i; j < nw; j += stride) {
        float4 v = w4[j];
        wo[j * 2 + 0] = __floats2half2_rn(v.x, v.y);
        wo[j * 2 + 1] = __floats2half2_rn(v.z, v.w);
    }
}

// ---------------------------------------------------------------------------
// fp16 mma.sync GEMM (2 CTAs/SM, 3-stage, single sync/kt) + fused scan
// ---------------------------------------------------------------------------
__global__ void __launch_bounds__(NTHR, 2) gemm_kernel(const float* __restrict__ bias)
{
    extern __shared__ __half smh[];
    float* smf = (float*)smh;
    const int tid  = threadIdx.x;
    const int wid  = tid >> 5;
    const int lane = tid & 31;
    const int g    = lane >> 2;
    const int c    = lane & 3;
    const int m0   = blockIdx.y * BM;
    const int h0   = blockIdx.x * BNR;
    const uint32_t sbase = smem_u32(smh);

    // cp.async chunk descriptors (16B = 8 halves): A 4/thread, B 4/thread
    const __half* gA[4]; uint32_t dA[4];
#pragma unroll
    for (int i = 0; i < 4; i++) {
        int ci = tid + i * NTHR;          // 0..1023
        int row = ci >> 3, ch = ci & 7;
        gA[i] = g_xh + (size_t)(m0 + row) * HIN + ch * 8;
        dA[i] = (uint32_t)(row * 144 + ch * 16);
    }
    const __half* gB[4]; uint32_t dB[4];
#pragma unroll
    for (int i = 0; i < 4; i++) {
        int ci = tid + i * NTHR;          // 0..1023
        int row = ci >> 3, ch = ci & 7;
        int wrow = (row < 64) ? (h0 + row) : (HD + h0 + row - 64);
        gB[i] = g_wh + (size_t)wrow * HIN + ch * 8;
        dB[i] = (uint32_t)(AHALF * 2 + row * 144 + ch * 16);
    }

#define ISSUE(KT) do {                                                        \
    int _kt = (KT);                                                           \
    if (_kt < KIT) {                                                          \
        uint32_t _s = sbase + (uint32_t)(_kt % STAGES) * (STAGEH * 2);        \
        _Pragma("unroll")                                                     \
        for (int _i = 0; _i < 4; _i++) cp16(_s + dA[_i], gA[_i] + _kt * BK);  \
        _Pragma("unroll")                                                     \
        for (int _i = 0; _i < 4; _i++) cp16(_s + dB[_i], gB[_i] + _kt * BK);  \
    }                                                                         \
    asm volatile("cp.async.commit_group;" ::: "memory");                      \
} while (0)

    ISSUE(0);
    ISSUE(1);

    // 8 warps: 4(M) x 2(Ncomb); warp tile 32 x 64 -> 2 Mtiles x 8 Ntiles
    const int mw = (wid >> 1) * 32;
    const int nw = (wid & 1) * 64;

    const int aj = lane >> 3;
    const int arow = mw + (aj & 1) * 8 + (lane & 7);
    const uint32_t aoff = (uint32_t)(arow * 144 + (aj >> 1) * 16);
    const int bj = lane >> 3;
    const int brow_base = nw + (bj >> 1) * 8 + (lane & 7);
    const uint32_t bkoff = (uint32_t)((bj & 1) * 16);

    float d[2][8][4];
#pragma unroll
    for (int mt = 0; mt < 2; mt++)
#pragma unroll
        for (int nt = 0; nt < 8; nt++)
#pragma unroll
            for (int q = 0; q < 4; q++) d[mt][nt][q] = 0.f;

    for (int kt = 0; kt < KIT; kt++) {
        asm volatile("cp.async.wait_group 1;" ::: "memory");
        __syncthreads();   // stage kt ready for all; stage kt-1 reads done
        ISSUE(kt + 2);     // overwrites stage (kt+2)%3 == (kt-1)%3 — safe

        const uint32_t sa = sbase + (uint32_t)(kt % STAGES) * (STAGEH * 2);
        const uint32_t sb = sa + AHALF * 2;

        uint32_t afc[2][4], afn[2][4];
#pragma unroll
        for (int mt = 0; mt < 2; mt++)
            ldsm4(afc[mt][0], afc[mt][1], afc[mt][2], afc[mt][3],
                  sa + aoff + (uint32_t)(mt * 16 * 144));

#pragma unroll
        for (int s16 = 0; s16 < 4; s16++) {
            const uint32_t kbyte = (uint32_t)(s16 * 32);
            if (s16 < 3) {
#pragma unroll
                for (int mt = 0; mt < 2; mt++)
                    ldsm4(afn[mt][0], afn[mt][1], afn[mt][2], afn[mt][3],
                          sa + aoff + (uint32_t)(mt * 16 * 144) + kbyte + 32);
            }
            uint32_t bf[8][2];
#pragma unroll
            for (int p = 0; p < 4; p++) {
                int ntp = p * 2;
                ldsm4(bf[ntp][0], bf[ntp][1], bf[ntp+1][0], bf[ntp+1][1],
                      sb + (uint32_t)((brow_base + ntp * 8) * 144) + bkoff + kbyte);
            }
#pragma unroll
            for (int mt = 0; mt < 2; mt++)
#pragma unroll
                for (int nt = 0; nt < 8; nt++) {
                    asm volatile(
                        "mma.sync.aligned.m16n8k16.row.col.f32.f16.f16.f32 "
                        "{%0,%1,%2,%3}, {%4,%5,%6,%7}, {%8,%9}, {%0,%1,%2,%3};"
                        : "+f"(d[mt][nt][0]), "+f"(d[mt][nt][1]),
                          "+f"(d[mt][nt][2]), "+f"(d[mt][nt][3])
                        : "r"(afc[mt][0]), "r"(afc[mt][1]), "r"(afc[mt][2]), "r"(afc[mt][3]),
                          "r"(bf[nt][0]), "r"(bf[nt][1]));
                }
#pragma unroll
            for (int mt = 0; mt < 2; mt++)
#pragma unroll
                for (int q = 0; q < 4; q++) afc[mt][q] = afn[mt][q];
        }
    }
    __syncthreads();

    // ---- step 1: acc -> smem tile (z | h_inter), pitch 132
#pragma unroll
    for (int mt = 0; mt < 2; mt++)
#pragma unroll
        for (int nt = 0; nt < 8; nt++) {
            int r   = mw + mt * 16 + g;
            int col = nw + nt * 8 + 2 * c;
            *(float2*)&smf[r * EPIPITCH + col]       = make_float2(d[mt][nt][0], d[mt][nt][1]);
            *(float2*)&smf[(r + 8) * EPIPITCH + col] = make_float2(d[mt][nt][2], d[mt][nt][3]);
        }
    __syncthreads();

    // ---- step 2: fused activation + segment-local scan; streaming stores
    const int sch = tid & 63;
    const int seg = tid >> 6;
    float* sPend = smf + SEGSM_OFF;             // [4][64]
    float* sVend = smf + SEGSM_OFF + 4 * 64;
    const float bz = __ldg(bias + h0 + sch);
    const float bh = __ldg(bias + HD + h0 + sch);
    {
        float P = 0.f, v = -FLT_MAX;
#pragma unroll 4
        for (int l = seg * 32; l < seg * 32 + 32; l++) {
            float z  = smf[l * EPIPITCH + sch]      + bz;
            float hi = smf[l * EPIPITCH + 64 + sch] + bh;
            float s  = fmaxf(-z, 0.f) + __logf(1.f + __expf(-fabsf(z)));
            float A  = -(z + s);
            float ltH = (hi >= 0.f) ? __logf(hi + 0.5f)
                                    : hi - __logf(1.f + __expf(hi));
            float B  = ltH - s;
            P += A;
            v = logaddexpf(A + v, B);
            size_t idx = (size_t)(m0 + l) * HD + h0 + sch;
            __stcs(&g_a[idx], P);
            __stcs(&g_b[idx], v);
        }
        sPend[seg * 64 + sch] = P;
        sVend[seg * 64 + sch] = v;
    }
    __syncthreads();

    // ---- step 3: combine seg summaries -> per-seg incoming + chunk endpoint
    if (tid < 64) {
        int n   = m0 >> 12;
        int cch = (m0 & (LSEQ - 1)) >> 7;
        float Pb = 0.f, V = -FLT_MAX;
#pragma unroll
        for (int s = 0; s < 4; s++) {
            float Pe = sPend[s * 64 + tid];
            float Ve = sVend[s * 64 + tid];
            size_t sidx = ((size_t)(cch * 4 + s) * NB + n) * HD + h0 + tid;
            g_segP[sidx] = Pb;
            g_segV[sidx] = V;
            V  = logaddexpf(Pe + V, Ve);
            Pb += Pe;
        }
        size_t eidx = ((size_t)n * HD + h0 + tid) * NCH + cch;
        g_Pend[eidx] = Pb;
        g_Vend[eidx] = V;
    }
}

// ---------------------------------------------------------------------------
// Scan phase 2: one warp per (n,h); Kogge-Stone scan over 32 chunk states
// ---------------------------------------------------------------------------
__global__ void __launch_bounds__(256) scan_p2_kernel(const float* __restrict__ hx)
{
    int w = (blockIdx.x * blockDim.x + threadIdx.x) >> 5;
    int lane = threadIdx.x & 31;
    if (w >= TCH) return;

    float P = g_Pend[(size_t)w * NCH + lane];
    float V = g_Vend[(size_t)w * NCH + lane];

#pragma unroll
    for (int dlt = 1; dlt < 32; dlt <<= 1) {
        float Pp = __shfl_up_sync(0xFFFFFFFF, P, dlt);
        float Vp = __shfl_up_sync(0xFFFFFFFF, V, dlt);
        if (lane >= dlt) {
            V = logaddexpf(P + Vp, V);
            P = P + Pp;
        }
    }
    float Pe = __shfl_up_sync(0xFFFFFFFF, P, 1);
    float Ve = __shfl_up_sync(0xFFFFFFFF, V, 1);
    if (lane == 0) { Pe = 0.f; Ve = -FLT_MAX; }

    float logh0 = __logf(hx[w]);
    g_init[lane * TCH + w] = logaddexpf(Pe + logh0, Ve);
}

// ---------------------------------------------------------------------------
// Scan phase 3: J = logaddexp(Pb+I, V); out = exp(logaddexp(Pl + J, vl))
// ---------------------------------------------------------------------------
__global__ void __launch_bounds__(256) scan_p3_kernel(float* __restrict__ out)
{
    size_t i = (size_t)blockIdx.x * blockDim.x + threadIdx.x;
    size_t stride = (size_t)gridDim.x * blockDim.x;
    const float4* pa4 = (const float4*)g_a;
    const float4* pb4 = (const float4*)g_b;
    const float4* pi4 = (const float4*)g_init;
    const float4* sp4 = (const float4*)g_segP;
    const float4* sv4 = (const float4*)g_segV;
    float4* out4 = (float4*)out;
    size_t total = (size_t)MTOT * HD / 4;

    for (size_t j = i; j < total; j += stride) {
        size_t row = j >> 8;
        int q = (int)(j & 255);
        int l = (int)(row & (LSEQ - 1));
        int n = (int)(row >> 12);
        int c = l >> 7;
        int s = (l >> 5) & 3;
        size_t tq = (size_t)n * (HD / 4) + q;
        float4 Pl = __ldcs(&pa4[j]);
        float4 vl = __ldcs(&pb4[j]);
        float4 I  = pi4[(size_t)c * (TCH / 4) + tq];
        float4 Pb = sp4[(size_t)(c * 4 + s) * (TCH / 4) + tq];
        float4 V  = sv4[(size_t)(c * 4 + s) * (TCH / 4) + tq];
        float4 o;
        o.x = __expf(logaddexpf(Pl.x + logaddexpf(Pb.x + I.x, V.x), vl.x));
        o.y = __expf(logaddexpf(Pl.y + logaddexpf(Pb.y + I.y, V.y), vl.y));
        o.z = __expf(logaddexpf(Pl.z + logaddexpf(Pb.z + I.z, V.z), vl.z));
        o.w = __expf(logaddexpf(Pl.w + logaddexpf(Pb.w + I.w, V.w), vl.w));
        __stcs(&out4[j], o);
    }
}

extern "C" void kernel_launch(void* const* d_in, const int* in_sizes, int n_in,
                              void* d_out, int out_size) {
    const float* x    = (const float*)d_in[0];
    const float* W    = (const float*)d_in[1];
    const float* bias = (const float*)d_in[2];
    const float* hx   = (const float*)d_in[3];
    float* out = (float*)d_out;

    cudaFuncSetAttribute(gemm_kernel,
                         cudaFuncAttributeMaxDynamicSharedMemorySize, SMEM_BYTES);

    cvt_kernel<<<2048, 256>>>(x, W);
    dim3 grid(HD / BNR, MTOT / BM);   // (16, 256)
    gemm_kernel<<<grid, NTHR, SMEM_BYTES>>>(bias);

    scan_p2_kernel<<<(TCH * 32) / 256, 256>>>(hx);
    scan_p3_kernel<<<4096, 256>>>(out);
}